// round 1
// baseline (speedup 1.0000x reference)
#include <cuda_runtime.h>
#include <math.h>
#include <stdint.h>

#define NTOK 16384
#define DFE 128
#define H1D 256
#define TT 20
#define NCH 10
#define KF 114      // 75 coord + 39 dihedral rows
#define MT 128      // tokens per layer-1 tile
#define OFF_COORD 128
#define OFF_DIH   1628
#define OFF_CHAIN 1667

// ---------------- scratch (static device globals; no allocation) ----------------
__device__ float g_tabA[TT * H1D];
__device__ float g_tabC[NCH * H1D];
__device__ float g_h1[NTOK * H1D];
__device__ float g_h2[NTOK * DFE];
__device__ float g_h3[NTOK * DFE];
__device__ int g_cnt[TT];
__device__ int g_off[TT + 1];
__device__ int g_cur[TT];
__device__ int g_perm[NTOK];

__constant__ float c_freq[6] = {1.0f, 2.0f, 3.0f, 1.0f, 0.5f, 1.0f / 3.0f};

// ---------------- sort-by-type pipeline ----------------
__global__ void k_zero() {
    int t = threadIdx.x;
    if (t < TT) g_cnt[t] = 0;
}

__global__ void k_hist(const int* __restrict__ seq) {
    __shared__ int h[TT];
    if (threadIdx.x < TT) h[threadIdx.x] = 0;
    __syncthreads();
    int i = blockIdx.x * blockDim.x + threadIdx.x;
    if (i < NTOK) atomicAdd(&h[seq[i]], 1);
    __syncthreads();
    if (threadIdx.x < TT) atomicAdd(&g_cnt[threadIdx.x], h[threadIdx.x]);
}

__global__ void k_scan() {
    int o = 0;
    for (int t = 0; t < TT; t++) {
        g_off[t] = o;
        g_cur[t] = o;
        o += g_cnt[t];
    }
    g_off[TT] = o;
}

__global__ void k_scatter(const int* __restrict__ seq) {
    int i = blockIdx.x * blockDim.x + threadIdx.x;
    if (i < NTOK) {
        int t = seq[i];
        int pos = atomicAdd(&g_cur[t], 1);
        g_perm[pos] = i;
    }
}

// ---------------- precompute type/chain contribution tables ----------------
__global__ void k_tables(const float* __restrict__ aa_emb, const float* __restrict__ chain_emb,
                         const float* __restrict__ W1, const float* __restrict__ b1) {
    int r = blockIdx.x, j = threadIdx.x;
    float acc = 0.f;
    if (r < TT) {
        const float* e = aa_emb + r * DFE;
#pragma unroll 8
        for (int k = 0; k < DFE; k++) acc += e[k] * W1[k * H1D + j];
        g_tabA[r * H1D + j] = acc + b1[j];
    } else {
        int c = r - TT;
        if (c != 0) {
            const float* e = chain_emb + c * DFE;
#pragma unroll 8
            for (int k = 0; k < DFE; k++) acc += e[k] * W1[(OFF_CHAIN + k) * H1D + j];
        }
        g_tabC[c * H1D + j] = acc;
    }
}

// ---------------- layer 1: type-grouped sparse GEMM ----------------
// grid = TT * 128; block (type, tile) handles up to 128 tokens of one type.
// smem: Ws[114][256] (coord rows for this type + shared dihedral rows),
//       Fs[114][128] (features, k-major), token/chain lists.
#define SMEM_H1 (KF * H1D * 4 + KF * MT * 4 + MT * 8)

__global__ void __launch_bounds__(512, 1)
k_h1(const float* __restrict__ xyz, const float* __restrict__ dih,
     const int* __restrict__ cidx, const float* __restrict__ ori,
     const float* __restrict__ W1) {
    int type = blockIdx.x >> 7;
    int tile = blockIdx.x & 127;
    int cnt = g_cnt[type];
    if (tile * MT >= cnt) return;
    int start = g_off[type] + tile * MT;
    int n = min(MT, cnt - tile * MT);

    extern __shared__ float sm[];
    float* Ws = sm;                      // [114][256]
    float* Fs = sm + KF * H1D;           // [114][128]
    int* toks = (int*)(Fs + KF * MT);    // [128]
    int* chains = toks + MT;             // [128]

    int tid = threadIdx.x;

    for (int i = tid; i < MT; i += 512) {
        int tok = (i < n) ? g_perm[start + i] : -1;
        toks[i] = tok;
        chains[i] = (tok >= 0) ? cidx[tok] : 0;
    }
    __syncthreads();

    // stage weights (coord block for this type + dihedral block), float4
    for (int i4 = tid; i4 < (KF * H1D) / 4; i4 += 512) {
        int r = i4 >> 6;
        int c = (i4 & 63) << 2;
        int gr = (r < 75) ? (OFF_COORD + type * 75 + r) : (OFF_DIH + r - 75);
        *(float4*)(Ws + r * H1D + c) = *(const float4*)(W1 + (size_t)gr * H1D + c);
    }

    // compute features into Fs[k][t] (k-major, conflict-free)
    for (int i = tid; i < KF * MT; i += 512) {
        int k = i >> 7;
        int t = i & 127;
        int tok = toks[t];
        float v = 0.f;
        if (tok >= 0) {
            if (k < 75) {
                int a = k / 3, c = k - a * 3;
                const float* xb = xyz + (size_t)tok * 75;
                const float* ob = ori + (size_t)tok * 9;
                float r0 = xb[a * 3 + 0] - xb[3];
                float r1 = xb[a * 3 + 1] - xb[4];
                float r2 = xb[a * 3 + 2] - xb[5];
                v = ob[c] * r0 + ob[3 + c] * r1 + ob[6 + c] * r2;
            } else {
                int kd = k - 75;
                int dm = kd / 13, q = kd - dm * 13;
                float x = dih[(size_t)tok * 3 + dm];
                if (q == 0) v = x;
                else if (q <= 6) v = sinf(c_freq[q - 1] * x);
                else v = cosf(c_freq[q - 7] * x);
            }
        }
        Fs[k * MT + t] = v;
    }
    __syncthreads();

    // 128 tokens x 256 cols, 512 threads, 8x8 per thread
    int cg = tid & 31;   // col group: cols cg*8 .. +7
    int rg = tid >> 5;   // row group: tokens rg*8 .. +7
    const float* wp = Ws + cg * 8;
    const float* fp = Fs + rg * 8;

    float acc[8][8];
#pragma unroll
    for (int i = 0; i < 8; i++)
#pragma unroll
        for (int j = 0; j < 8; j++) acc[i][j] = 0.f;

#pragma unroll 2
    for (int k = 0; k < KF; k++) {
        float4 w0 = *(const float4*)(wp + k * H1D);
        float4 w1 = *(const float4*)(wp + k * H1D + 4);
        float4 f0 = *(const float4*)(fp + k * MT);
        float4 f1 = *(const float4*)(fp + k * MT + 4);
        float fv[8] = {f0.x, f0.y, f0.z, f0.w, f1.x, f1.y, f1.z, f1.w};
        float wv[8] = {w0.x, w0.y, w0.z, w0.w, w1.x, w1.y, w1.z, w1.w};
#pragma unroll
        for (int i = 0; i < 8; i++)
#pragma unroll
            for (int j = 0; j < 8; j++) acc[i][j] = fmaf(fv[i], wv[j], acc[i][j]);
    }

    float4 ta0 = *(const float4*)(g_tabA + type * H1D + cg * 8);
    float4 ta1 = *(const float4*)(g_tabA + type * H1D + cg * 8 + 4);
    float ta[8] = {ta0.x, ta0.y, ta0.z, ta0.w, ta1.x, ta1.y, ta1.z, ta1.w};

#pragma unroll
    for (int i = 0; i < 8; i++) {
        int p = rg * 8 + i;
        int tok = toks[p];
        if (tok < 0) continue;
        const float* tc = g_tabC + chains[p] * H1D + cg * 8;
        float4 o0, o1;
        o0.x = fmaxf(acc[i][0] + ta[0] + tc[0], 0.f);
        o0.y = fmaxf(acc[i][1] + ta[1] + tc[1], 0.f);
        o0.z = fmaxf(acc[i][2] + ta[2] + tc[2], 0.f);
        o0.w = fmaxf(acc[i][3] + ta[3] + tc[3], 0.f);
        o1.x = fmaxf(acc[i][4] + ta[4] + tc[4], 0.f);
        o1.y = fmaxf(acc[i][5] + ta[5] + tc[5], 0.f);
        o1.z = fmaxf(acc[i][6] + ta[6] + tc[6], 0.f);
        o1.w = fmaxf(acc[i][7] + ta[7] + tc[7], 0.f);
        float* op = g_h1 + (size_t)tok * H1D + cg * 8;
        *(float4*)op = o0;
        *(float4*)(op + 4) = o1;
    }
}

// ---------------- layers 2-4: dense fp32 GEMM, M=16384, N=128 ----------------
// 128x128 tile, 256 threads, 8x8 micro-tile, double-buffered smem, K-tile 16.
template <int K, bool RELU>
__global__ void __launch_bounds__(256, 2)
k_mlp(const float* __restrict__ A, const float* __restrict__ W,
      const float* __restrict__ bias, float* __restrict__ out) {
    __shared__ float As[2][16 * 128];
    __shared__ float Wsm[2][16 * 128];
    int tid = threadIdx.x;
    int row0 = blockIdx.x * 128;

    int lr = tid & 127;           // A loader: row
    int lk = (tid >> 7) * 8;      // A loader: k offset (0 or 8)
    int wk = tid >> 5;            // W loader: k row (0..7, and +8)
    int wc = (tid & 31) * 4;      // W loader: col

    const float* Abase = A + (size_t)(row0 + lr) * K + lk;
    const float* Wbase = W + (size_t)wk * 128 + wc;

    int rg = tid >> 4;            // row group
    int cg = tid & 15;            // col group

    float acc[8][8];
#pragma unroll
    for (int i = 0; i < 8; i++)
#pragma unroll
        for (int j = 0; j < 8; j++) acc[i][j] = 0.f;

    constexpr int NT = K / 16;
    float4 pa0, pa1, pw0, pw1;

    // prologue: load tile 0
    pa0 = *(const float4*)(Abase);
    pa1 = *(const float4*)(Abase + 4);
    pw0 = *(const float4*)(Wbase);
    pw1 = *(const float4*)(Wbase + 8 * 128);
    {
        float* as = As[0];
        as[(lk + 0) * 128 + lr] = pa0.x;
        as[(lk + 1) * 128 + lr] = pa0.y;
        as[(lk + 2) * 128 + lr] = pa0.z;
        as[(lk + 3) * 128 + lr] = pa0.w;
        as[(lk + 4) * 128 + lr] = pa1.x;
        as[(lk + 5) * 128 + lr] = pa1.y;
        as[(lk + 6) * 128 + lr] = pa1.z;
        as[(lk + 7) * 128 + lr] = pa1.w;
        *(float4*)(Wsm[0] + wk * 128 + wc) = pw0;
        *(float4*)(Wsm[0] + (wk + 8) * 128 + wc) = pw1;
    }
    __syncthreads();

    for (int kt = 0; kt < NT; kt++) {
        if (kt + 1 < NT) {
            pa0 = *(const float4*)(Abase + (kt + 1) * 16);
            pa1 = *(const float4*)(Abase + (kt + 1) * 16 + 4);
            pw0 = *(const float4*)(Wbase + (size_t)(kt + 1) * 16 * 128);
            pw1 = *(const float4*)(Wbase + (size_t)(kt + 1) * 16 * 128 + 8 * 128);
        }
        const float* as = As[kt & 1];
        const float* ws = Wsm[kt & 1];
#pragma unroll
        for (int k = 0; k < 16; k++) {
            float4 a0 = *(const float4*)(as + k * 128 + rg * 8);
            float4 a1 = *(const float4*)(as + k * 128 + rg * 8 + 4);
            float4 w0 = *(const float4*)(ws + k * 128 + cg * 8);
            float4 w1 = *(const float4*)(ws + k * 128 + cg * 8 + 4);
            float av[8] = {a0.x, a0.y, a0.z, a0.w, a1.x, a1.y, a1.z, a1.w};
            float wv[8] = {w0.x, w0.y, w0.z, w0.w, w1.x, w1.y, w1.z, w1.w};
#pragma unroll
            for (int i = 0; i < 8; i++)
#pragma unroll
                for (int j = 0; j < 8; j++) acc[i][j] = fmaf(av[i], wv[j], acc[i][j]);
        }
        if (kt + 1 < NT) {
            float* asn = As[(kt + 1) & 1];
            asn[(lk + 0) * 128 + lr] = pa0.x;
            asn[(lk + 1) * 128 + lr] = pa0.y;
            asn[(lk + 2) * 128 + lr] = pa0.z;
            asn[(lk + 3) * 128 + lr] = pa0.w;
            asn[(lk + 4) * 128 + lr] = pa1.x;
            asn[(lk + 5) * 128 + lr] = pa1.y;
            asn[(lk + 6) * 128 + lr] = pa1.z;
            asn[(lk + 7) * 128 + lr] = pa1.w;
            *(float4*)(Wsm[(kt + 1) & 1] + wk * 128 + wc) = pw0;
            *(float4*)(Wsm[(kt + 1) & 1] + (wk + 8) * 128 + wc) = pw1;
        }
        __syncthreads();
    }

    float4 b0 = *(const float4*)(bias + cg * 8);
    float4 b1v = *(const float4*)(bias + cg * 8 + 4);
    float bb[8] = {b0.x, b0.y, b0.z, b0.w, b1v.x, b1v.y, b1v.z, b1v.w};

#pragma unroll
    for (int i = 0; i < 8; i++) {
        float4 o0, o1;
        o0.x = acc[i][0] + bb[0];
        o0.y = acc[i][1] + bb[1];
        o0.z = acc[i][2] + bb[2];
        o0.w = acc[i][3] + bb[3];
        o1.x = acc[i][4] + bb[4];
        o1.y = acc[i][5] + bb[5];
        o1.z = acc[i][6] + bb[6];
        o1.w = acc[i][7] + bb[7];
        if (RELU) {
            o0.x = fmaxf(o0.x, 0.f); o0.y = fmaxf(o0.y, 0.f);
            o0.z = fmaxf(o0.z, 0.f); o0.w = fmaxf(o0.w, 0.f);
            o1.x = fmaxf(o1.x, 0.f); o1.y = fmaxf(o1.y, 0.f);
            o1.z = fmaxf(o1.z, 0.f); o1.w = fmaxf(o1.w, 0.f);
        }
        float* op = out + (size_t)(row0 + rg * 8 + i) * 128 + cg * 8;
        *(float4*)op = o0;
        *(float4*)(op + 4) = o1;
    }
}

// ---------------- host ----------------
extern "C" void kernel_launch(void* const* d_in, const int* in_sizes, int n_in,
                              void* d_out, int out_size) {
    const int* seq = (const int*)d_in[0];
    const float* xyz = (const float*)d_in[1];
    const float* dih = (const float*)d_in[2];
    const int* cidx = (const int*)d_in[3];
    const float* ori = (const float*)d_in[4];
    // d_in[5] = atom_mask (unused by reference math)
    const float* aa_emb = (const float*)d_in[6];
    const float* chain_emb = (const float*)d_in[7];
    const float* W1 = (const float*)d_in[8];
    const float* b1 = (const float*)d_in[9];
    const float* W2 = (const float*)d_in[10];
    const float* b2 = (const float*)d_in[11];
    const float* W3 = (const float*)d_in[12];
    const float* b3 = (const float*)d_in[13];
    const float* W4 = (const float*)d_in[14];
    const float* b4 = (const float*)d_in[15];
    float* out = (float*)d_out;

    cudaFuncSetAttribute(k_h1, cudaFuncAttributeMaxDynamicSharedMemorySize, SMEM_H1);

    float *h1p, *h2p, *h3p;
    cudaGetSymbolAddress((void**)&h1p, g_h1);
    cudaGetSymbolAddress((void**)&h2p, g_h2);
    cudaGetSymbolAddress((void**)&h3p, g_h3);

    k_zero<<<1, 32>>>();
    k_hist<<<32, 512>>>(seq);
    k_scan<<<1, 1>>>();
    k_scatter<<<32, 512>>>(seq);
    k_tables<<<30, 256>>>(aa_emb, chain_emb, W1, b1);
    k_h1<<<TT * 128, 512, SMEM_H1>>>(xyz, dih, cidx, ori, W1);
    k_mlp<256, true><<<128, 256>>>(h1p, W2, b2, h2p);
    k_mlp<128, true><<<128, 256>>>(h2p, W3, b3, h3p);
    k_mlp<128, false><<<128, 256>>>(h3p, W4, b4, out);
}

// round 4
// speedup vs baseline: 1.3288x; 1.3288x over previous
#include <cuda_runtime.h>
#include <cuda_bf16.h>
#include <math.h>
#include <stdint.h>

#define NTOK 16384
#define H1D 256
#define TT 20
#define OFF_COORD 128
#define OFF_DIH   1628
#define OFF_CHAIN 1667

typedef unsigned short u16;
typedef unsigned int   u32;

// ---------------- scratch (static device globals; no allocation) ----------------
__device__ float g_tabA[TT * H1D];
__device__ float g_tabC[10 * H1D];
__device__ float g_h1[NTOK * H1D];
__device__ float g_h2[NTOK * 128];
__device__ float g_h3[NTOK * 128];
__device__ int g_cnt[TT];
__device__ int g_off[TT + 1];
__device__ int g_cur[TT];
__device__ int g_perm[NTOK];
// pre-split weights (bf16 hi/lo), transposed to [n][k]
__device__ u16 g_w1tH[TT * 256 * 128], g_w1tL[TT * 256 * 128];
__device__ u16 g_w2tH[128 * 256],      g_w2tL[128 * 256];
__device__ u16 g_w3tH[128 * 128],      g_w3tL[128 * 128];
__device__ u16 g_w4tH[128 * 128],      g_w4tL[128 * 128];

__constant__ float c_freq[6] = {1.0f, 2.0f, 3.0f, 1.0f, 0.5f, 1.0f / 3.0f};

// ---------------- helpers ----------------
__device__ __forceinline__ u32 smem_u32(const void* p) {
    u32 a;
    asm("{ .reg .u64 t; cvta.to.shared.u64 t, %1; cvt.u32.u64 %0, t; }" : "=r"(a) : "l"(p));
    return a;
}
__device__ __forceinline__ void split1(float x, u32& h, u32& l) {
    __nv_bfloat16 hb = __float2bfloat16(x);
    h = (u32)__bfloat16_as_ushort(hb);
    l = (u32)__bfloat16_as_ushort(__float2bfloat16(x - __bfloat162float(hb)));
}
__device__ __forceinline__ void split8(const float* x, uint4& hi, uint4& lo) {
    u32 h[8], l[8];
#pragma unroll
    for (int i = 0; i < 8; i++) split1(x[i], h[i], l[i]);
    hi.x = h[0] | (h[1] << 16); hi.y = h[2] | (h[3] << 16);
    hi.z = h[4] | (h[5] << 16); hi.w = h[6] | (h[7] << 16);
    lo.x = l[0] | (l[1] << 16); lo.y = l[2] | (l[3] << 16);
    lo.z = l[4] | (l[5] << 16); lo.w = l[6] | (l[7] << 16);
}

// swizzled byte offset of 16B chunk c8 (0..15) in row r (rows of 128 bf16 = 256B)
__device__ __forceinline__ u32 swoff(int r, int c8) {
    return (u32)r * 256u + ((((u32)c8) & 8u) | ((((u32)c8) ^ (u32)r) & 7u)) * 16u;
}

__device__ __forceinline__ void ldsm_x4(u32 addr, u32 (&r)[4]) {
    asm volatile("ldmatrix.sync.aligned.m8n8.x4.shared.b16 {%0,%1,%2,%3}, [%4];"
        : "=r"(r[0]), "=r"(r[1]), "=r"(r[2]), "=r"(r[3]) : "r"(addr));
}
__device__ __forceinline__ void ldsm_x2(u32 addr, u32 (&r)[2]) {
    asm volatile("ldmatrix.sync.aligned.m8n8.x2.shared.b16 {%0,%1}, [%2];"
        : "=r"(r[0]), "=r"(r[1]) : "r"(addr));
}
__device__ __forceinline__ void mma_bf16(float (&d)[4], const u32 (&a)[4], const u32 (&b)[2]) {
    asm volatile("mma.sync.aligned.m16n8k16.row.col.f32.bf16.bf16.f32 "
        "{%0,%1,%2,%3}, {%4,%5,%6,%7}, {%8,%9}, {%0,%1,%2,%3};"
        : "+f"(d[0]), "+f"(d[1]), "+f"(d[2]), "+f"(d[3])
        : "r"(a[0]), "r"(a[1]), "r"(a[2]), "r"(a[3]), "r"(b[0]), "r"(b[1]));
}

// 128x128x128 warp GEMM (bf16x3) ; warp tile 32x64, acc[2][8][4]
__device__ __forceinline__ void warp_gemm128(u32 Ahi, u32 Alo, u32 Bhi, u32 Blo,
                                             int m0w, int n0w, int lane,
                                             float (&acc)[2][8][4]) {
    int arow = (lane & 7) + ((lane >> 3) & 1) * 8;
    int akoff = (lane >> 4) * 8;
    int l15 = lane & 15;
    int brow = l15 & 7;
    int bkoff = (l15 >> 3) * 8;
#pragma unroll
    for (int kc = 0; kc < 8; kc++) {
        int k0 = kc * 16;
        u32 aH[2][4], aL[2][4];
#pragma unroll
        for (int mi = 0; mi < 2; mi++) {
            u32 off = swoff(m0w + mi * 16 + arow, (k0 + akoff) >> 3);
            ldsm_x4(Ahi + off, aH[mi]);
            ldsm_x4(Alo + off, aL[mi]);
        }
        u32 bH[8][2], bL[8][2];
#pragma unroll
        for (int nj = 0; nj < 8; nj++) {
            u32 off = swoff(n0w + nj * 8 + brow, (k0 + bkoff) >> 3);
            ldsm_x2(Bhi + off, bH[nj]);
            ldsm_x2(Blo + off, bL[nj]);
        }
#pragma unroll
        for (int mi = 0; mi < 2; mi++)
#pragma unroll
            for (int nj = 0; nj < 8; nj++) {
                mma_bf16(acc[mi][nj], aH[mi], bH[nj]);
                mma_bf16(acc[mi][nj], aL[mi], bH[nj]);
                mma_bf16(acc[mi][nj], aH[mi], bL[nj]);
            }
    }
}

// ---------------- sort-by-type pipeline ----------------
__global__ void k_zero() { if (threadIdx.x < TT) g_cnt[threadIdx.x] = 0; }

__global__ void k_hist(const int* __restrict__ seq) {
    __shared__ int h[TT];
    if (threadIdx.x < TT) h[threadIdx.x] = 0;
    __syncthreads();
    int i = blockIdx.x * blockDim.x + threadIdx.x;
    if (i < NTOK) atomicAdd(&h[seq[i]], 1);
    __syncthreads();
    if (threadIdx.x < TT) atomicAdd(&g_cnt[threadIdx.x], h[threadIdx.x]);
}

__global__ void k_scan() {
    int o = 0;
    for (int t = 0; t < TT; t++) { g_off[t] = o; g_cur[t] = o; o += g_cnt[t]; }
    g_off[TT] = o;
}

__global__ void k_scatter(const int* __restrict__ seq) {
    int i = blockIdx.x * blockDim.x + threadIdx.x;
    if (i < NTOK) {
        int t = seq[i];
        g_perm[atomicAdd(&g_cur[t], 1)] = i;
    }
}

// ---------------- precompute type/chain contribution tables (fp32) ----------------
__global__ void k_tables(const float* __restrict__ aa_emb, const float* __restrict__ chain_emb,
                         const float* __restrict__ W1, const float* __restrict__ b1) {
    int r = blockIdx.x, j = threadIdx.x;
    float acc = 0.f;
    if (r < TT) {
        const float* e = aa_emb + r * 128;
#pragma unroll 8
        for (int k = 0; k < 128; k++) acc += e[k] * W1[k * H1D + j];
        g_tabA[r * H1D + j] = acc + b1[j];
    } else {
        int c = r - TT;
        if (c != 0) {
            const float* e = chain_emb + c * 128;
#pragma unroll 8
            for (int k = 0; k < 128; k++) acc += e[k] * W1[(OFF_CHAIN + k) * H1D + j];
        }
        g_tabC[c * H1D + j] = acc;
    }
}

// ---------------- weight pre-split kernels ----------------
__global__ void k_split_w1(const float* __restrict__ W1) {
    int b = blockIdx.x;            // t*256 + n
    int t = b >> 8, n = b & 255;
    int k = threadIdx.x;           // 128
    float v = 0.f;
    if (k < 75) v = W1[(size_t)(OFF_COORD + t * 75 + k) * H1D + n];
    else if (k < 114) v = W1[(size_t)(OFF_DIH + k - 75) * H1D + n];
    u32 h, l; split1(v, h, l);
    size_t idx = (size_t)b * 128 + k;
    g_w1tH[idx] = (u16)h; g_w1tL[idx] = (u16)l;
}

__global__ void k_split_wt(const float* __restrict__ src, int K, int N,
                           u16* __restrict__ dh, u16* __restrict__ dl) {
    int n = blockIdx.x, k = threadIdx.x;
    u32 h, l; split1(src[(size_t)k * N + n], h, l);
    dh[(size_t)n * K + k] = (u16)h;
    dl[(size_t)n * K + k] = (u16)l;
}

// ---------------- layer 1: type-grouped tensor GEMM (mma.sync) ----------------
#define H1_AHI 0
#define H1_ALO 32768
#define H1_BHI 65536
#define H1_BLO 98304
#define H1_TOKS 131072
#define H1_CH   131584
#define H1_TA   132096
#define H1_TC   133120
#define SMEM_H1 143360

__global__ void __launch_bounds__(256)
k_h1_mma(const float* __restrict__ xyz, const float* __restrict__ dih,
         const int* __restrict__ cidx, const float* __restrict__ ori) {
    int type = blockIdx.x >> 5;
    int tile = blockIdx.x & 31;
    int cnt = g_cnt[type];
    if (tile * 128 >= cnt) return;
    int start = g_off[type] + tile * 128;
    int n = min(128, cnt - tile * 128);

    extern __shared__ char smem[];
    u32 sb = smem_u32(smem);
    int tid = threadIdx.x, wid = tid >> 5, lane = tid & 31;
    int* toks_s = (int*)(smem + H1_TOKS);
    int* ch_s = (int*)(smem + H1_CH);
    float* tabA_s = (float*)(smem + H1_TA);
    float* tabC_s = (float*)(smem + H1_TC);

    if (tid < 128) {
        int tok = (tid < n) ? g_perm[start + tid] : -1;
        toks_s[tid] = tok;
        ch_s[tid] = (tok >= 0) ? cidx[tok] : 0;
    }
    for (int i = tid; i < 256; i += 256) tabA_s[i] = g_tabA[type * H1D + i];
    for (int i = tid; i < 2560; i += 256) tabC_s[i] = g_tabC[i];
    __syncthreads();

    // A fill: features (75 coord + 39 dihedral enc + pad to 128), fp32 -> hi/lo
    {
        int t = tid & 127;
        int k0 = (tid >> 7) * 64;
        int tok = toks_s[t];
        const float* xb = xyz + (size_t)(tok < 0 ? 0 : tok) * 75;
        const float* ob = ori + (size_t)(tok < 0 ? 0 : tok) * 9;
        float d0 = 0.f, d1 = 0.f, d2 = 0.f, cax = 0.f, cay = 0.f, caz = 0.f;
        if (tok >= 0) {
            d0 = dih[(size_t)tok * 3]; d1 = dih[(size_t)tok * 3 + 1]; d2 = dih[(size_t)tok * 3 + 2];
            cax = xb[3]; cay = xb[4]; caz = xb[5];
        }
        for (int kk = 0; kk < 64; kk++) {
            int k = k0 + kk;
            float v = 0.f;
            if (tok >= 0) {
                if (k < 75) {
                    int a = k / 3, c = k - a * 3;
                    float r0 = xb[a * 3 + 0] - cax;
                    float r1 = xb[a * 3 + 1] - cay;
                    float r2 = xb[a * 3 + 2] - caz;
                    v = ob[c] * r0 + ob[3 + c] * r1 + ob[6 + c] * r2;
                } else if (k < 114) {
                    int kd = k - 75;
                    int dm = kd / 13, q = kd - dm * 13;
                    float x = (dm == 0) ? d0 : (dm == 1) ? d1 : d2;
                    if (q == 0) v = x;
                    else if (q <= 6) v = sinf(c_freq[q - 1] * x);
                    else v = cosf(c_freq[q - 7] * x);
                }
            }
            u32 h, l; split1(v, h, l);
            u32 o = swoff(t, k >> 3) + (k & 7) * 2;
            *(u16*)&smem[H1_AHI + o] = (u16)h;
            *(u16*)&smem[H1_ALO + o] = (u16)l;
        }
    }
    // B fill pass 0
    {
        int r = tid & 127;
        int c0 = (tid >> 7) * 8;
        const uint4* sH = (const uint4*)(g_w1tH + (size_t)(type * 256 + r) * 128);
        const uint4* sL = (const uint4*)(g_w1tL + (size_t)(type * 256 + r) * 128);
#pragma unroll
        for (int i = 0; i < 8; i++) {
            u32 o = swoff(r, c0 + i);
            *(uint4*)&smem[H1_BHI + o] = sH[c0 + i];
            *(uint4*)&smem[H1_BLO + o] = sL[c0 + i];
        }
    }
    __syncthreads();

    int m0w = (wid >> 1) * 32, n0w = (wid & 1) * 64;
    float acc[2][8][4];
#pragma unroll
    for (int a = 0; a < 2; a++)
#pragma unroll
        for (int b = 0; b < 8; b++)
#pragma unroll
            for (int c = 0; c < 4; c++) acc[a][b][c] = 0.f;

    warp_gemm128(sb + H1_AHI, sb + H1_ALO, sb + H1_BHI, sb + H1_BLO, m0w, n0w, lane, acc);
    __syncthreads();

    // fill B pass 1 + epilogue pass 0
    {
        int r = tid & 127;
        int c0 = (tid >> 7) * 8;
        const uint4* sH = (const uint4*)(g_w1tH + (size_t)(type * 256 + 128 + r) * 128);
        const uint4* sL = (const uint4*)(g_w1tL + (size_t)(type * 256 + 128 + r) * 128);
#pragma unroll
        for (int i = 0; i < 8; i++) {
            u32 o = swoff(r, c0 + i);
            *(uint4*)&smem[H1_BHI + o] = sH[c0 + i];
            *(uint4*)&smem[H1_BLO + o] = sL[c0 + i];
        }
    }
#pragma unroll
    for (int pass = 0; pass < 2; pass++) {
        if (pass == 1) {
#pragma unroll
            for (int a = 0; a < 2; a++)
#pragma unroll
                for (int b = 0; b < 8; b++)
#pragma unroll
                    for (int c = 0; c < 4; c++) acc[a][b][c] = 0.f;
            __syncthreads();
            warp_gemm128(sb + H1_AHI, sb + H1_ALO, sb + H1_BHI, sb + H1_BLO, m0w, n0w, lane, acc);
        }
        // epilogue for this pass
#pragma unroll
        for (int mi = 0; mi < 2; mi++)
#pragma unroll
            for (int nj = 0; nj < 8; nj++) {
                int c_l = n0w + nj * 8 + (lane & 3) * 2;
                int col = pass * 128 + c_l;
                float ta0 = tabA_s[col], ta1 = tabA_s[col + 1];
#pragma unroll
                for (int h = 0; h < 2; h++) {
                    int r_l = m0w + mi * 16 + (lane >> 2) + h * 8;
                    int tok = toks_s[r_l];
                    if (tok >= 0) {
                        int ch = ch_s[r_l];
                        float2 v;
                        v.x = fmaxf(acc[mi][nj][2 * h] + ta0 + tabC_s[ch * 256 + col], 0.f);
                        v.y = fmaxf(acc[mi][nj][2 * h + 1] + ta1 + tabC_s[ch * 256 + col + 1], 0.f);
                        *(float2*)(g_h1 + (size_t)tok * H1D + col) = v;
                    }
                }
            }
    }
}

// ---------------- layers 2-4: dense tensor GEMM (mma.sync), N=128 ----------------
#define MP_AHI 0
#define MP_ALO 32768
#define MP_BHI 65536
#define MP_BLO 98304
#define MP_BS  131072
#define SMEM_MLP 131584

template <int KT, bool RELU>
__global__ void __launch_bounds__(256)
k_mlp_mma(const float* __restrict__ A, const u16* __restrict__ WtH, const u16* __restrict__ WtL,
          const float* __restrict__ bias, float* __restrict__ out) {
    extern __shared__ char smem[];
    u32 sb = smem_u32(smem);
    int tid = threadIdx.x, wid = tid >> 5, lane = tid & 31;
    int row0 = blockIdx.x * 128;
    float* bs = (float*)(smem + MP_BS);
    if (tid < 128) bs[tid] = bias[tid];

    int m0w = (wid >> 1) * 32, n0w = (wid & 1) * 64;
    float acc[2][8][4];
#pragma unroll
    for (int a = 0; a < 2; a++)
#pragma unroll
        for (int b = 0; b < 8; b++)
#pragma unroll
            for (int c = 0; c < 4; c++) acc[a][b][c] = 0.f;

    constexpr int NC = KT / 128;
#pragma unroll
    for (int kc = 0; kc < NC; kc++) {
        if (kc > 0) __syncthreads();  // protect smem from previous gemm reads
        // A fill
        {
            int r = tid & 127;
            int c0 = (tid >> 7) * 8;
            const float* src = A + (size_t)(row0 + r) * KT + kc * 128;
#pragma unroll
            for (int i = 0; i < 8; i++) {
                int c8 = c0 + i;
                float xs[8];
                float4 f0 = *(const float4*)(src + c8 * 8);
                float4 f1 = *(const float4*)(src + c8 * 8 + 4);
                xs[0] = f0.x; xs[1] = f0.y; xs[2] = f0.z; xs[3] = f0.w;
                xs[4] = f1.x; xs[5] = f1.y; xs[6] = f1.z; xs[7] = f1.w;
                uint4 hi, lo; split8(xs, hi, lo);
                u32 o = swoff(r, c8);
                *(uint4*)&smem[MP_AHI + o] = hi;
                *(uint4*)&smem[MP_ALO + o] = lo;
            }
        }
        // B fill
        {
            int r = tid & 127;
            int c0 = (tid >> 7) * 8;
            const uint4* sH = (const uint4*)(WtH + (size_t)r * KT + kc * 128);
            const uint4* sL = (const uint4*)(WtL + (size_t)r * KT + kc * 128);
#pragma unroll
            for (int i = 0; i < 8; i++) {
                u32 o = swoff(r, c0 + i);
                *(uint4*)&smem[MP_BHI + o] = sH[c0 + i];
                *(uint4*)&smem[MP_BLO + o] = sL[c0 + i];
            }
        }
        __syncthreads();
        warp_gemm128(sb + MP_AHI, sb + MP_ALO, sb + MP_BHI, sb + MP_BLO, m0w, n0w, lane, acc);
    }

    // epilogue
#pragma unroll
    for (int mi = 0; mi < 2; mi++)
#pragma unroll
        for (int nj = 0; nj < 8; nj++) {
            int c_l = n0w + nj * 8 + (lane & 3) * 2;
            float b0 = bs[c_l], b1 = bs[c_l + 1];
#pragma unroll
            for (int h = 0; h < 2; h++) {
                int r_l = m0w + mi * 16 + (lane >> 2) + h * 8;
                float2 v;
                v.x = acc[mi][nj][2 * h] + b0;
                v.y = acc[mi][nj][2 * h + 1] + b1;
                if (RELU) { v.x = fmaxf(v.x, 0.f); v.y = fmaxf(v.y, 0.f); }
                *(float2*)(out + (size_t)(row0 + r_l) * 128 + c_l) = v;
            }
        }
}

// ---------------- host ----------------
extern "C" void kernel_launch(void* const* d_in, const int* in_sizes, int n_in,
                              void* d_out, int out_size) {
    const int* seq = (const int*)d_in[0];
    const float* xyz = (const float*)d_in[1];
    const float* dih = (const float*)d_in[2];
    const int* cidx = (const int*)d_in[3];
    const float* ori = (const float*)d_in[4];
    const float* aa_emb = (const float*)d_in[6];
    const float* chain_emb = (const float*)d_in[7];
    const float* W1 = (const float*)d_in[8];
    const float* b1 = (const float*)d_in[9];
    const float* W2 = (const float*)d_in[10];
    const float* b2 = (const float*)d_in[11];
    const float* W3 = (const float*)d_in[12];
    const float* b3 = (const float*)d_in[13];
    const float* W4 = (const float*)d_in[14];
    const float* b4 = (const float*)d_in[15];
    float* out = (float*)d_out;

    cudaFuncSetAttribute(k_h1_mma, cudaFuncAttributeMaxDynamicSharedMemorySize, SMEM_H1);
    cudaFuncSetAttribute(k_mlp_mma<256, true>, cudaFuncAttributeMaxDynamicSharedMemorySize, SMEM_MLP);
    cudaFuncSetAttribute(k_mlp_mma<128, true>, cudaFuncAttributeMaxDynamicSharedMemorySize, SMEM_MLP);
    cudaFuncSetAttribute(k_mlp_mma<128, false>, cudaFuncAttributeMaxDynamicSharedMemorySize, SMEM_MLP);

    float *h1p, *h2p, *h3p;
    cudaGetSymbolAddress((void**)&h1p, g_h1);
    cudaGetSymbolAddress((void**)&h2p, g_h2);
    cudaGetSymbolAddress((void**)&h3p, g_h3);
    u16 *w2h, *w2l, *w3h, *w3l, *w4h, *w4l;
    cudaGetSymbolAddress((void**)&w2h, g_w2tH); cudaGetSymbolAddress((void**)&w2l, g_w2tL);
    cudaGetSymbolAddress((void**)&w3h, g_w3tH); cudaGetSymbolAddress((void**)&w3l, g_w3tL);
    cudaGetSymbolAddress((void**)&w4h, g_w4tH); cudaGetSymbolAddress((void**)&w4l, g_w4tL);

    k_zero<<<1, 32>>>();
    k_hist<<<32, 512>>>(seq);
    k_scan<<<1, 1>>>();
    k_scatter<<<32, 512>>>(seq);
    k_tables<<<30, 256>>>(aa_emb, chain_emb, W1, b1);
    k_split_w1<<<TT * 256, 128>>>(W1);
    k_split_wt<<<128, 256>>>(W2, 256, 128, w2h, w2l);
    k_split_wt<<<128, 128>>>(W3, 128, 128, w3h, w3l);
    k_split_wt<<<128, 128>>>(W4, 128, 128, w4h, w4l);
    k_h1_mma<<<TT * 32, 256, SMEM_H1>>>(xyz, dih, cidx, ori);
    k_mlp_mma<256, true><<<128, 256, SMEM_MLP>>>(h1p, w2h, w2l, b2, h2p);
    k_mlp_mma<128, true><<<128, 256, SMEM_MLP>>>(h2p, w3h, w3l, b3, h3p);
    k_mlp_mma<128, false><<<128, 256, SMEM_MLP>>>(h3p, w4h, w4l, b4, out);
}

// round 5
// speedup vs baseline: 1.4349x; 1.0798x over previous
#include <cuda_runtime.h>
#include <cuda_bf16.h>
#include <math.h>
#include <stdint.h>

#define NTOK 16384
#define H1D 256
#define TT 20
#define OFF_COORD 128
#define OFF_DIH   1628
#define OFF_CHAIN 1667

typedef unsigned short u16;
typedef unsigned int   u32;

// ---------------- scratch (static device globals; no allocation) ----------------
__device__ float g_tabA[TT * H1D];
__device__ float g_tabC[10 * H1D];
__device__ int g_cnt[TT];
__device__ int g_off[TT + 1];
__device__ int g_perm[NTOK];
__device__ int g_bhist[32 * TT];
__device__ int g_base[32 * TT];
// pre-split weights (bf16 hi/lo), transposed to [n][k]
__device__ u16 g_w1tH[TT * 256 * 128], g_w1tL[TT * 256 * 128];
__device__ u16 g_w2tH[128 * 256],      g_w2tL[128 * 256];
__device__ u16 g_w3tH[128 * 128],      g_w3tL[128 * 128];
__device__ u16 g_w4tH[128 * 128],      g_w4tL[128 * 128];

__constant__ float c_freq[6] = {1.0f, 2.0f, 3.0f, 1.0f, 0.5f, 1.0f / 3.0f};

// ---------------- helpers ----------------
__device__ __forceinline__ u32 smem_u32(const void* p) {
    u32 a;
    asm("{ .reg .u64 t; cvta.to.shared.u64 t, %1; cvt.u32.u64 %0, t; }" : "=r"(a) : "l"(p));
    return a;
}
__device__ __forceinline__ void split1(float x, u32& h, u32& l) {
    __nv_bfloat16 hb = __float2bfloat16(x);
    h = (u32)__bfloat16_as_ushort(hb);
    l = (u32)__bfloat16_as_ushort(__float2bfloat16(x - __bfloat162float(hb)));
}
// swizzled byte offset of 16B chunk c8 (0..15) in row r (rows of 128 bf16 = 256B)
__device__ __forceinline__ u32 swoff(int r, int c8) {
    return (u32)r * 256u + ((((u32)c8) & 8u) | ((((u32)c8) ^ (u32)r) & 7u)) * 16u;
}
__device__ __forceinline__ void ldsm_x4(u32 addr, u32 (&r)[4]) {
    asm volatile("ldmatrix.sync.aligned.m8n8.x4.shared.b16 {%0,%1,%2,%3}, [%4];"
        : "=r"(r[0]), "=r"(r[1]), "=r"(r[2]), "=r"(r[3]) : "r"(addr));
}
__device__ __forceinline__ void ldsm_x2(u32 addr, u32 (&r)[2]) {
    asm volatile("ldmatrix.sync.aligned.m8n8.x2.shared.b16 {%0,%1}, [%2];"
        : "=r"(r[0]), "=r"(r[1]) : "r"(addr));
}
__device__ __forceinline__ void mma_bf16(float (&d)[4], const u32 (&a)[4], const u32 (&b)[2]) {
    asm volatile("mma.sync.aligned.m16n8k16.row.col.f32.bf16.bf16.f32 "
        "{%0,%1,%2,%3}, {%4,%5,%6,%7}, {%8,%9}, {%0,%1,%2,%3};"
        : "+f"(d[0]), "+f"(d[1]), "+f"(d[2]), "+f"(d[3])
        : "r"(a[0]), "r"(a[1]), "r"(a[2]), "r"(a[3]), "r"(b[0]), "r"(b[1]));
}

// 128x128x128 warp GEMM (bf16x3); warp tile 32x64, acc[2][8][4] accumulates
__device__ __forceinline__ void warp_gemm128(u32 Ahi, u32 Alo, u32 Bhi, u32 Blo,
                                             int m0w, int n0w, int lane,
                                             float (&acc)[2][8][4]) {
    int arow = (lane & 7) + ((lane >> 3) & 1) * 8;
    int akoff = (lane >> 4) * 8;
    int l15 = lane & 15;
    int brow = l15 & 7;
    int bkoff = (l15 >> 3) * 8;
#pragma unroll
    for (int kc = 0; kc < 8; kc++) {
        int k0 = kc * 16;
        u32 aH[2][4], aL[2][4];
#pragma unroll
        for (int mi = 0; mi < 2; mi++) {
            u32 off = swoff(m0w + mi * 16 + arow, (k0 + akoff) >> 3);
            ldsm_x4(Ahi + off, aH[mi]);
            ldsm_x4(Alo + off, aL[mi]);
        }
        u32 bH[8][2], bL[8][2];
#pragma unroll
        for (int nj = 0; nj < 8; nj++) {
            u32 off = swoff(n0w + nj * 8 + brow, (k0 + bkoff) >> 3);
            ldsm_x2(Bhi + off, bH[nj]);
            ldsm_x2(Blo + off, bL[nj]);
        }
#pragma unroll
        for (int mi = 0; mi < 2; mi++)
#pragma unroll
            for (int nj = 0; nj < 8; nj++) {
                mma_bf16(acc[mi][nj], aH[mi], bH[nj]);
                mma_bf16(acc[mi][nj], aL[mi], bH[nj]);
                mma_bf16(acc[mi][nj], aH[mi], bL[nj]);
            }
    }
}

// ---------------- fused prep kernel ----------------
// blocks [0,32): per-strip hist (512 tokens each)
// blocks [32,62): tabA/tabC
// blocks [62,222): W1 transpose-split (20 types x 8 n-blocks)
// blocks [222,230): W2 transpose-split, [230,234): W3, [234,238): W4
__global__ void __launch_bounds__(256)
k_prep(const int* __restrict__ seq, const float* __restrict__ aa_emb,
       const float* __restrict__ chain_emb, const float* __restrict__ W1,
       const float* __restrict__ b1, const float* __restrict__ W2,
       const float* __restrict__ W3, const float* __restrict__ W4) {
    int b = blockIdx.x, tid = threadIdx.x;
    if (b < 32) {
        __shared__ int h[TT];
        if (tid < TT) h[tid] = 0;
        __syncthreads();
        int base = b * 512;
        atomicAdd(&h[seq[base + tid]], 1);
        atomicAdd(&h[seq[base + 256 + tid]], 1);
        __syncthreads();
        if (tid < TT) g_bhist[b * TT + tid] = h[tid];
        return;
    }
    if (b < 62) {
        int r = b - 32, j = tid;
        float acc = 0.f;
        if (r < TT) {
            const float* e = aa_emb + r * 128;
#pragma unroll 8
            for (int k = 0; k < 128; k++) acc += e[k] * W1[k * H1D + j];
            g_tabA[r * H1D + j] = acc + b1[j];
        } else {
            int c = r - TT;
            if (c != 0) {
                const float* e = chain_emb + c * 128;
#pragma unroll 8
                for (int k = 0; k < 128; k++) acc += e[k] * W1[(OFF_CHAIN + k) * H1D + j];
            }
            g_tabC[c * H1D + j] = acc;
        }
        return;
    }
    __shared__ float s[128][33];
    const float* src;
    u16 *dh, *dl;
    int Kd, n0glob, kskip = 0, srcN, srcRow0 = 0;
    bool w1 = false;
    int t = 0;
    if (b < 222) {
        int bb = b - 62;
        t = bb >> 3;
        int nb = bb & 7;
        w1 = true;
        src = W1; srcN = 256; n0glob = nb * 32;
        dh = g_w1tH + (size_t)t * 256 * 128; dl = g_w1tL + (size_t)t * 256 * 128;
        Kd = 128;
    } else if (b < 230) {
        int bb = b - 222;
        int nb = bb & 3, kb = bb >> 2;
        src = W2; srcN = 128; n0glob = nb * 32; srcRow0 = kb * 128; kskip = kb * 128;
        dh = g_w2tH; dl = g_w2tL; Kd = 256;
    } else if (b < 234) {
        int nb = b - 230;
        src = W3; srcN = 128; n0glob = nb * 32;
        dh = g_w3tH; dl = g_w3tL; Kd = 128;
    } else {
        int nb = b - 234;
        src = W4; srcN = 128; n0glob = nb * 32;
        dh = g_w4tH; dl = g_w4tL; Kd = 128;
    }
    // load 128k x 32n tile (coalesced over n)
#pragma unroll
    for (int it = 0; it < 16; it++) {
        int idx = tid + it * 256;
        int k = idx >> 5, nn = idx & 31;
        float v;
        if (w1) {
            if (k < 75) v = src[(size_t)(OFF_COORD + t * 75 + k) * srcN + n0glob + nn];
            else if (k < 114) v = src[(size_t)(OFF_DIH + k - 75) * srcN + n0glob + nn];
            else v = 0.f;
        } else {
            v = src[(size_t)(srcRow0 + k) * srcN + n0glob + nn];
        }
        s[k][nn] = v;
    }
    __syncthreads();
    // write transposed [n][k], packed u32 (2 k per store)
#pragma unroll
    for (int it = 0; it < 8; it++) {
        int idx = tid + it * 256;
        int n = idx >> 6, kk = (idx & 63) * 2;
        u32 h0, l0, h1, l1;
        split1(s[kk][n], h0, l0);
        split1(s[kk + 1][n], h1, l1);
        size_t o = (size_t)(n0glob + n) * Kd + kskip + kk;
        *(u32*)(dh + o) = h0 | (h1 << 16);
        *(u32*)(dl + o) = l0 | (l1 << 16);
    }
}

// ---------------- scan: per-(strip,type) bases ----------------
__global__ void k_scan2() {
    __shared__ int sh[32][TT];
    __shared__ int spref[32][TT];
    __shared__ int scnt[TT];
    __shared__ int soff[TT + 1];
    int tid = threadIdx.x;
    if (tid < 640) sh[tid / TT][tid % TT] = g_bhist[tid];
    __syncthreads();
    if (tid < TT) {
        int run = 0;
#pragma unroll
        for (int b = 0; b < 32; b++) { spref[b][tid] = run; run += sh[b][tid]; }
        scnt[tid] = run;
    }
    __syncthreads();
    if (tid == 0) {
        int o = 0;
        for (int t = 0; t < TT; t++) { soff[t] = o; o += scnt[t]; }
        soff[TT] = o;
    }
    __syncthreads();
    if (tid < TT) { g_cnt[tid] = scnt[tid]; g_off[tid] = soff[tid]; }
    if (tid == 0) g_off[TT] = soff[TT];
    if (tid < 640) g_base[tid] = soff[tid % TT] + spref[tid / TT][tid % TT];
}

// ---------------- scatter ----------------
__global__ void __launch_bounds__(512)
k_scatter2(const int* __restrict__ seq) {
    __shared__ int cur[TT];
    int tid = threadIdx.x;
    if (tid < TT) cur[tid] = g_base[blockIdx.x * TT + tid];
    __syncthreads();
    int i = blockIdx.x * 512 + tid;
    int t = seq[i];
    int pos = atomicAdd(&cur[t], 1);
    g_perm[pos] = i;
}

// ---------------- fused main kernel: all 4 layers per 128-token tile ----------------
// regions (bytes from smem base): R0 0, R1 65536, R2 131072 (each: HI +0, LO +32768)
// extras at 196608: tabA 1K, tabC 10K, bs2/3/4 512 each, toks 512, ch 512
#define R0 0
#define R1 65536
#define R2 131072
#define EX_TA   196608
#define EX_TC   197632
#define EX_B2   207872
#define EX_B3   208384
#define EX_B4   208896
#define EX_TOK  209408
#define EX_CH   209920
#define SMEM_MAIN 210432

struct Frag { float a[2][8][4]; };

__global__ void __launch_bounds__(256)
k_main(const float* __restrict__ xyz, const float* __restrict__ dih,
       const int* __restrict__ cidx, const float* __restrict__ ori,
       const float* __restrict__ b2, const float* __restrict__ b3,
       const float* __restrict__ b4, float* __restrict__ out) {
    int type = blockIdx.x >> 5;
    int tile = blockIdx.x & 31;
    int cnt = g_cnt[type];
    if (tile * 128 >= cnt) return;
    int start = g_off[type] + tile * 128;
    int n = min(128, cnt - tile * 128);

    extern __shared__ char smem[];
    u32 sb = smem_u32(smem);
    int tid = threadIdx.x, wid = tid >> 5, lane = tid & 31;
    int* toks_s = (int*)(smem + EX_TOK);
    int* ch_s = (int*)(smem + EX_CH);
    float* tabA_s = (float*)(smem + EX_TA);
    float* tabC_s = (float*)(smem + EX_TC);
    float* bs2 = (float*)(smem + EX_B2);
    float* bs3 = (float*)(smem + EX_B3);
    float* bs4 = (float*)(smem + EX_B4);

    if (tid < 128) {
        int tok = (tid < n) ? g_perm[start + tid] : -1;
        toks_s[tid] = tok;
        ch_s[tid] = (tok >= 0) ? cidx[tok] : 0;
        bs2[tid] = b2[tid];
        bs3[tid] = b3[tid];
        bs4[tid] = b4[tid];
    }
    for (int i = tid; i < 256; i += 256) tabA_s[i] = g_tabA[type * H1D + i];
    for (int i = tid; i < 2560; i += 256) tabC_s[i] = g_tabC[i];
    __syncthreads();

    // ---- L1 A fill (features) into R0 ----
    {
        int t = tid & 127;
        int k0 = (tid >> 7) * 64;
        int tok = toks_s[t];
        const float* xb = xyz + (size_t)(tok < 0 ? 0 : tok) * 75;
        const float* ob = ori + (size_t)(tok < 0 ? 0 : tok) * 9;
        float d0 = 0.f, d1 = 0.f, d2 = 0.f, cax = 0.f, cay = 0.f, caz = 0.f;
        if (tok >= 0) {
            d0 = dih[(size_t)tok * 3]; d1 = dih[(size_t)tok * 3 + 1]; d2 = dih[(size_t)tok * 3 + 2];
            cax = xb[3]; cay = xb[4]; caz = xb[5];
        }
        for (int kk = 0; kk < 64; kk++) {
            int k = k0 + kk;
            float v = 0.f;
            if (tok >= 0) {
                if (k < 75) {
                    int a = k / 3, c = k - a * 3;
                    float r0 = xb[a * 3 + 0] - cax;
                    float r1 = xb[a * 3 + 1] - cay;
                    float r2 = xb[a * 3 + 2] - caz;
                    v = ob[c] * r0 + ob[3 + c] * r1 + ob[6 + c] * r2;
                } else if (k < 114) {
                    int kd = k - 75;
                    int dm = kd / 13, q = kd - dm * 13;
                    float x = (dm == 0) ? d0 : (dm == 1) ? d1 : d2;
                    if (q == 0) v = x;
                    else if (q <= 6) v = sinf(c_freq[q - 1] * x);
                    else v = cosf(c_freq[q - 7] * x);
                }
            }
            u32 h, l;
            split1(v, h, l);
            u32 o = swoff(t, k >> 3) + (k & 7) * 2;
            *(u16*)&smem[R0 + o] = (u16)h;
            *(u16*)&smem[R0 + 32768 + o] = (u16)l;
        }
    }

    int r_fill = tid & 127;
    int c0_fill = (tid >> 7) * 8;

    // B fill helper (macro-ish lambda): stride in u16 elems
#define FILL_B(DST, SRCH, SRCL, STRIDE, KOFF) do { \
        const uint4* _sH = (const uint4*)((SRCH) + (size_t)r_fill * (STRIDE) + (KOFF)); \
        const uint4* _sL = (const uint4*)((SRCL) + (size_t)r_fill * (STRIDE) + (KOFF)); \
        _Pragma("unroll") \
        for (int i = 0; i < 8; i++) { \
            u32 o = swoff(r_fill, c0_fill + i); \
            *(uint4*)&smem[(DST) + o] = _sH[c0_fill + i]; \
            *(uint4*)&smem[(DST) + 32768 + o] = _sL[c0_fill + i]; \
        } \
    } while (0)

    // L1 B pass0 (W1 rows n 0..127 of this type)
    FILL_B(R1, g_w1tH + (size_t)type * 256 * 128, g_w1tL + (size_t)type * 256 * 128, 128, 0);
    __syncthreads();

    int m0w = (wid >> 1) * 32, n0w = (wid & 1) * 64;
    float acc[2][8][4];

#define ZERO_ACC() do { \
        _Pragma("unroll") for (int _a = 0; _a < 2; _a++) \
        _Pragma("unroll") for (int _b = 0; _b < 8; _b++) \
        _Pragma("unroll") for (int _c = 0; _c < 4; _c++) acc[_a][_b][_c] = 0.f; \
    } while (0)

    // epilogue -> smem bf16 hi/lo tile
#define EPI_SMEM(DST, EXPR) do { \
        _Pragma("unroll") \
        for (int mi = 0; mi < 2; mi++) \
        _Pragma("unroll") \
        for (int nj = 0; nj < 8; nj++) { \
            int c_l = n0w + nj * 8 + (lane & 3) * 2; \
            _Pragma("unroll") \
            for (int hh = 0; hh < 2; hh++) { \
                int r_l = m0w + mi * 16 + (lane >> 2) + hh * 8; \
                float v0x = acc[mi][nj][2 * hh], v1x = acc[mi][nj][2 * hh + 1]; \
                float v0 = (EXPR(v0x, r_l, c_l)); \
                float v1 = (EXPR(v1x, r_l, (c_l + 1))); \
                u32 h0, l0, h1, l1; \
                split1(v0, h0, l0); split1(v1, h1, l1); \
                u32 o = swoff(r_l, c_l >> 3) + (c_l & 7) * 2; \
                *(u32*)&smem[(DST) + o] = h0 | (h1 << 16); \
                *(u32*)&smem[(DST) + 32768 + o] = l0 | (l1 << 16); \
            } \
        } \
    } while (0)

    // ---- L1 pass0 ----
    ZERO_ACC();
    warp_gemm128(sb + R0, sb + R0 + 32768, sb + R1, sb + R1 + 32768, m0w, n0w, lane, acc);
    __syncthreads();
    // epi pass0 -> R2 (h1 cols 0..127); refill R1 with W1 rows 128..255
#define L1EXPR0(v, r, c) fmaxf((v) + tabA_s[(c)] + tabC_s[ch_s[(r)] * 256 + (c)], 0.f)
    EPI_SMEM(R2, L1EXPR0);
    FILL_B(R1, g_w1tH + (size_t)(type * 256 + 128) * 128, g_w1tL + (size_t)(type * 256 + 128) * 128, 128, 0);
    __syncthreads();

    // ---- L1 pass1 ----
    ZERO_ACC();
    warp_gemm128(sb + R0, sb + R0 + 32768, sb + R1, sb + R1 + 32768, m0w, n0w, lane, acc);
    __syncthreads();
    // epi pass1 -> R0 (h1 cols 128..255, overwrites features); refill R1 with W2 k-chunk0
#define L1EXPR1(v, r, c) fmaxf((v) + tabA_s[128 + (c)] + tabC_s[ch_s[(r)] * 256 + 128 + (c)], 0.f)
    EPI_SMEM(R0, L1EXPR1);
    FILL_B(R1, g_w2tH, g_w2tL, 256, 0);
    __syncthreads();

    // ---- L2 (K=256: chunk0 A=R2, chunk1 A=R0) ----
    ZERO_ACC();
    warp_gemm128(sb + R2, sb + R2 + 32768, sb + R1, sb + R1 + 32768, m0w, n0w, lane, acc);
    __syncthreads();
    FILL_B(R1, g_w2tH, g_w2tL, 256, 128);
    __syncthreads();
    warp_gemm128(sb + R0, sb + R0 + 32768, sb + R1, sb + R1 + 32768, m0w, n0w, lane, acc);
    __syncthreads();
    // epi -> h2 into R1; fill R2 = W3
#define ACTEXPR2(v, r, c) fmaxf((v) + bs2[(c)], 0.f)
    EPI_SMEM(R1, ACTEXPR2);
    FILL_B(R2, g_w3tH, g_w3tL, 128, 0);
    __syncthreads();

    // ---- L3 ----
    ZERO_ACC();
    warp_gemm128(sb + R1, sb + R1 + 32768, sb + R2, sb + R2 + 32768, m0w, n0w, lane, acc);
    __syncthreads();
    // epi -> h3 into R0; fill R2 = W4
#define ACTEXPR3(v, r, c) fmaxf((v) + bs3[(c)], 0.f)
    EPI_SMEM(R0, ACTEXPR3);
    FILL_B(R2, g_w4tH, g_w4tL, 128, 0);
    __syncthreads();

    // ---- L4 ----
    ZERO_ACC();
    warp_gemm128(sb + R0, sb + R0 + 32768, sb + R2, sb + R2 + 32768, m0w, n0w, lane, acc);

    // final epilogue -> global
#pragma unroll
    for (int mi = 0; mi < 2; mi++)
#pragma unroll
        for (int nj = 0; nj < 8; nj++) {
            int c_l = n0w + nj * 8 + (lane & 3) * 2;
            float bb0 = bs4[c_l], bb1 = bs4[c_l + 1];
#pragma unroll
            for (int hh = 0; hh < 2; hh++) {
                int r_l = m0w + mi * 16 + (lane >> 2) + hh * 8;
                int tok = toks_s[r_l];
                if (tok >= 0) {
                    float2 v;
                    v.x = acc[mi][nj][2 * hh] + bb0;
                    v.y = acc[mi][nj][2 * hh + 1] + bb1;
                    *(float2*)(out + (size_t)tok * 128 + c_l) = v;
                }
            }
        }
}

// ---------------- host ----------------
extern "C" void kernel_launch(void* const* d_in, const int* in_sizes, int n_in,
                              void* d_out, int out_size) {
    const int* seq = (const int*)d_in[0];
    const float* xyz = (const float*)d_in[1];
    const float* dih = (const float*)d_in[2];
    const int* cidx = (const int*)d_in[3];
    const float* ori = (const float*)d_in[4];
    const float* aa_emb = (const float*)d_in[6];
    const float* chain_emb = (const float*)d_in[7];
    const float* W1 = (const float*)d_in[8];
    const float* b1 = (const float*)d_in[9];
    const float* W2 = (const float*)d_in[10];
    const float* b2 = (const float*)d_in[11];
    const float* W3 = (const float*)d_in[12];
    const float* b3 = (const float*)d_in[13];
    const float* W4 = (const float*)d_in[14];
    const float* b4 = (const float*)d_in[15];
    float* out = (float*)d_out;

    cudaFuncSetAttribute(k_main, cudaFuncAttributeMaxDynamicSharedMemorySize, SMEM_MAIN);

    k_prep<<<238, 256>>>(seq, aa_emb, chain_emb, W1, b1, W2, W3, W4);
    k_scan2<<<1, 640>>>();
    k_scatter2<<<32, 512>>>(seq);
    k_main<<<TT * 32, 256, SMEM_MAIN>>>(xyz, dih, cidx, ori, b2, b3, b4, out);
}